// round 16
// baseline (speedup 1.0000x reference)
#include <cuda_runtime.h>
#include <cuda_bf16.h>
#include <cstdint>

#define N0 585728
#define N1 22528
#define N2 2048
#define E1 563200
#define E2 20480
#define IN_C 602
#define HID 256
#define OUT_C 41
#define KP 608           // padded half-K (602 -> 608)
#define KTOT 1216        // 2*KP
#define NKT 38           // KTOT/32 k-tiles
#define CAP1 96          // bucket capacity layer1 (Poisson λ=25, >8σ)
#define CAP2 64          // layer2 (λ=10)

// -------- scratch (static device globals; no allocation) --------
// g_cnt1/g_cnt2 are zero-initialized at module load and SELF-CLEANED:
// k_agg1 / k_l2 reset them to 0 after use, restoring the invariant for
// the next (graph-replayed) call. No k_zero kernel needed.
__device__ __align__(16) __nv_bfloat162 g_a1b[(size_t)N1 * (KP / 2)];  // agg1 bf16 [N1][608]
__device__ __align__(16) __nv_bfloat162 g_xb[(size_t)N1 * (KP / 2)];   // x_dst bf16 [N1][608]
__device__ __align__(16) __nv_bfloat16 g_wbT[(size_t)HID * KTOT];      // W^T bf16 [256][1216]
__device__ __align__(16) float g_h[(size_t)N1 * HID];
__device__ int g_cnt1[N1];
__device__ int g_bkt1[(size_t)N1 * CAP1];
__device__ int g_cnt2[N2];
__device__ int g_bkt2[(size_t)N2 * CAP2];

// ---------------- bucket fill (both layers, one launch) ---------------------
__global__ void k_fill_all(const int* __restrict__ ei1, const int* __restrict__ ei2) {
    int e = blockIdx.x * blockDim.x + threadIdx.x;
    if (e < E1) {
        int dst = ei1[E1 + e];
        int p = atomicAdd(&g_cnt1[dst], 1);
        if (p < CAP1) g_bkt1[(size_t)dst * CAP1 + p] = ei1[e];
    } else if (e < E1 + E2) {
        int f = e - E1;
        int dst = ei2[E2 + f];
        int p = atomicAdd(&g_cnt2[dst], 1);
        if (p < CAP2) g_bkt2[(size_t)dst * CAP2 + p] = ei2[f];
    }
}

// ---------------- weight prep: g_wbT[n][k] bf16, concat+pad -----------------
__global__ void k_prep(const float* __restrict__ Wl1, const float* __restrict__ Wr1) {
    int idx = blockIdx.x * blockDim.x + threadIdx.x;   // k*256+n
    if (idx >= KTOT * HID) return;
    int k = idx >> 8, n = idx & 255;
    float v = 0.f;
    if (k < IN_C)                      v = Wl1[(size_t)k * HID + n];
    else if (k >= KP && k < KP + IN_C) v = Wr1[(size_t)(k - KP) * HID + n];
    g_wbT[(size_t)n * KTOT + k] = __float2bfloat16(v);
}

// ---------------- x_dst -> bf16 padded ----------------
__global__ void k_xcast(const float* __restrict__ x) {
    int idx = blockIdx.x * blockDim.x + threadIdx.x;   // word index, [N1*304]
    if (idx >= N1 * (KP / 2)) return;
    int row = idx / (KP / 2), w = idx % (KP / 2);
    int c = w * 2;
    float a = (c < IN_C)     ? x[(size_t)row * IN_C + c] : 0.f;
    float b = (c + 1 < IN_C) ? x[(size_t)row * IN_C + c + 1] : 0.f;
    g_xb[idx] = __floats2bfloat162_rn(a, b);
}

// ---------------- layer-1 mean aggregation -> bf16 padded -------------------
__global__ void __launch_bounds__(128) k_agg1(const float* __restrict__ x) {
    int dst = blockIdx.x;
    int t = threadIdx.x;                       // 128 threads
    int deg = g_cnt1[dst];
    __syncthreads();                           // all threads have read deg
    if (t == 0) g_cnt1[dst] = 0;               // self-clean for next call
    int n = min(deg, CAP1);
    const int* bkt = &g_bkt1[(size_t)dst * CAP1];
    float2 acc0 = {0.f, 0.f}, acc1 = {0.f, 0.f}, acc2 = {0.f, 0.f};
    const float2* xb = reinterpret_cast<const float2*>(x);   // 301 float2/row
    int f2 = t + 256;
    bool g2 = (f2 < 301);
    int i = 0;
    for (; i + 1 < n; i += 2) {
        long long r0 = (long long)bkt[i] * 301;
        long long r1 = (long long)bkt[i + 1] * 301;
        float2 a = __ldg(&xb[r0 + t]);
        float2 b = __ldg(&xb[r0 + t + 128]);
        float2 c = g2 ? __ldg(&xb[r0 + f2]) : make_float2(0.f, 0.f);
        float2 d = __ldg(&xb[r1 + t]);
        float2 g = __ldg(&xb[r1 + t + 128]);
        float2 h = g2 ? __ldg(&xb[r1 + f2]) : make_float2(0.f, 0.f);
        acc0.x += a.x + d.x; acc0.y += a.y + d.y;
        acc1.x += b.x + g.x; acc1.y += b.y + g.y;
        acc2.x += c.x + h.x; acc2.y += c.y + h.y;
    }
    if (i < n) {
        long long r0 = (long long)bkt[i] * 301;
        float2 a = __ldg(&xb[r0 + t]);
        float2 b = __ldg(&xb[r0 + t + 128]);
        acc0.x += a.x; acc0.y += a.y;
        acc1.x += b.x; acc1.y += b.y;
        if (g2) { float2 c = __ldg(&xb[r0 + f2]); acc2.x += c.x; acc2.y += c.y; }
    }
    float inv = (deg > 0) ? 1.0f / (float)deg : 0.0f;
    __nv_bfloat162* ob = g_a1b + (long long)dst * (KP / 2);    // 304 words/row
    ob[t]       = __floats2bfloat162_rn(acc0.x * inv, acc0.y * inv);
    ob[t + 128] = __floats2bfloat162_rn(acc1.x * inv, acc1.y * inv);
    if (t < 48) {
        int w2 = t + 256;
        ob[w2] = __floats2bfloat162_rn((w2 < 301) ? acc2.x * inv : 0.f,
                                       (w2 < 301) ? acc2.y * inv : 0.f);
    }
}

// ---------------- MMA / ldmatrix / cp.async helpers ----------------
__device__ __forceinline__ void mma_bf16(float& c0, float& c1, float& c2, float& c3,
                                         unsigned a0, unsigned a1, unsigned a2, unsigned a3,
                                         unsigned b0, unsigned b1) {
    asm volatile("mma.sync.aligned.m16n8k16.row.col.f32.bf16.bf16.f32 "
                 "{%0,%1,%2,%3}, {%4,%5,%6,%7}, {%8,%9}, {%0,%1,%2,%3};"
                 : "+f"(c0), "+f"(c1), "+f"(c2), "+f"(c3)
                 : "r"(a0), "r"(a1), "r"(a2), "r"(a3), "r"(b0), "r"(b1));
}
__device__ __forceinline__ void ldsm4(unsigned* r, unsigned addr) {
    asm volatile("ldmatrix.sync.aligned.m8n8.x4.shared.b16 {%0,%1,%2,%3}, [%4];"
                 : "=r"(r[0]), "=r"(r[1]), "=r"(r[2]), "=r"(r[3]) : "r"(addr));
}
__device__ __forceinline__ void cpa16(unsigned saddr, const void* g) {
    asm volatile("cp.async.cg.shared.global [%0], [%1], 16;" :: "r"(saddr), "l"(g));
}
__device__ __forceinline__ void cpa_commit() { asm volatile("cp.async.commit_group;"); }

// ---------------- fused GEMM1 (bf16 MMA, 128x128 tile, 3-stage cp.async) ----
// h = relu([agg1 | x_dst] @ [Wl1;Wr1] + bl1)
// M=22528, K=1216 (padded), N=256. Block 128x128, 8 warps (4m x 2n), warp 32x64.
#define KSW 20
#define NSTG 3
__global__ void __launch_bounds__(256) k_gemm1(const float* __restrict__ bl1) {
    __shared__ __align__(16) unsigned As[NSTG][128 * KSW];   // 30720 B
    __shared__ __align__(16) unsigned Bs[NSTG][128 * KSW];   // 30720 B
    int tid = threadIdx.x;
    int bm = blockIdx.x * 128;
    int bn = blockIdx.y * 128;
    int warp = tid >> 5, lane = tid & 31;
    int wm = (warp & 3) * 32;
    int wn = (warp >> 2) * 64;
    int gid = lane >> 2, tig = lane & 3;

    // cp.async per-thread coords (2 chunks/thread for each of A and B)
    int ar = tid >> 1;                 // row
    int ac = (tid & 1) * 2;            // first 16B chunk (of 4/row)

    const __nv_bfloat16* a1p = reinterpret_cast<const __nv_bfloat16*>(g_a1b);
    const __nv_bfloat16* xbp = reinterpret_cast<const __nv_bfloat16*>(g_xb);

    float acc[2][8][4];
#pragma unroll
    for (int mt = 0; mt < 2; mt++)
#pragma unroll
        for (int nt = 0; nt < 8; nt++)
#pragma unroll
            for (int r = 0; r < 4; r++) acc[mt][nt][r] = 0.f;

    unsigned sA[NSTG], sB[NSTG];
#pragma unroll
    for (int s = 0; s < NSTG; s++) {
        sA[s] = (unsigned)__cvta_generic_to_shared(&As[s][0]);
        sB[s] = (unsigned)__cvta_generic_to_shared(&Bs[s][0]);
    }

    // ldmatrix lane address components
    int a_ro = (lane & 7) + ((lane >> 3) & 1) * 8;
    int a_kw = (lane >> 4) * 4;
    int aoffw[2];
#pragma unroll
    for (int mt = 0; mt < 2; mt++) aoffw[mt] = (wm + mt * 16 + a_ro) * KSW + a_kw;
    int b_ro = (lane & 7) + ((lane >> 4) << 3);
    int b_kw = ((lane >> 3) & 1) * 4;
    int boffw[4];
#pragma unroll
    for (int p = 0; p < 4; p++) boffw[p] = (wn + p * 16 + b_ro) * KSW + b_kw;

    auto load_tile = [&](int buf, int kt) {
        const __nv_bfloat16* src = (kt < 19) ? a1p : xbp;
        int k0 = ((kt < 19) ? kt : kt - 19) * 32;
#pragma unroll
        for (int i = 0; i < 2; i++) {
            int c = ac + i;
            const void* g = src + ((size_t)(bm + ar)) * KP + k0 + c * 8;
            cpa16(sA[buf] + (ar * KSW + c * 4) * 4, g);
        }
#pragma unroll
        for (int i = 0; i < 2; i++) {
            int c = ac + i;
            const void* g = g_wbT + ((size_t)(bn + ar)) * KTOT + kt * 32 + c * 8;
            cpa16(sB[buf] + (ar * KSW + c * 4) * 4, g);
        }
    };

    load_tile(0, 0); cpa_commit();
    load_tile(1, 1); cpa_commit();

    for (int kt = 0; kt < NKT; kt++) {
        int st = kt % NSTG;
        asm volatile("cp.async.wait_group 1;");
        __syncthreads();
        if (kt + 2 < NKT) { load_tile((kt + 2) % NSTG, kt + 2); cpa_commit(); }

#pragma unroll
        for (int half = 0; half < 2; half++) {
            unsigned af[2][4], bf[4][4];
#pragma unroll
            for (int mt = 0; mt < 2; mt++)
                ldsm4(af[mt], sA[st] + (aoffw[mt] + half * 8) * 4);
#pragma unroll
            for (int p = 0; p < 4; p++)
                ldsm4(bf[p], sB[st] + (boffw[p] + half * 8) * 4);
#pragma unroll
            for (int mt = 0; mt < 2; mt++)
#pragma unroll
                for (int nt = 0; nt < 8; nt++) {
                    int p = nt >> 1, q = (nt & 1) * 2;
                    mma_bf16(acc[mt][nt][0], acc[mt][nt][1], acc[mt][nt][2], acc[mt][nt][3],
                             af[mt][0], af[mt][1], af[mt][2], af[mt][3],
                             bf[p][q], bf[p][q + 1]);
                }
        }
    }

    // epilogue: bias + relu
#pragma unroll
    for (int nt = 0; nt < 8; nt++) {
        int c = bn + wn + nt * 8 + tig * 2;
        float b0 = bl1[c], b1 = bl1[c + 1];
#pragma unroll
        for (int mt = 0; mt < 2; mt++) {
            int r0 = bm + wm + mt * 16 + gid;
            float2 o0, o1;
            o0.x = fmaxf(acc[mt][nt][0] + b0, 0.f);
            o0.y = fmaxf(acc[mt][nt][1] + b1, 0.f);
            o1.x = fmaxf(acc[mt][nt][2] + b0, 0.f);
            o1.y = fmaxf(acc[mt][nt][3] + b1, 0.f);
            *reinterpret_cast<float2*>(&g_h[(long long)r0 * 256 + c]) = o0;
            *reinterpret_cast<float2*>(&g_h[(long long)(r0 + 8) * 256 + c]) = o1;
        }
    }
}

// ---------------- fused layer 2: agg2 + GEMM2 + bias + log_softmax ----------
__global__ void __launch_bounds__(64) k_l2(const float* __restrict__ Wl2,
                                           const float* __restrict__ bl2,
                                           const float* __restrict__ Wr2,
                                           float* __restrict__ out) {
    __shared__ __align__(16) float sA[HID];
    __shared__ __align__(16) float sH[HID];
    __shared__ float sO[OUT_C];
    __shared__ float s_mx, s_ls;
    int row = blockIdx.x, t = threadIdx.x;    // 64 threads, one float4 lane each

    int deg = g_cnt2[row];
    int n = min(deg, CAP2);
    const int* bkt = &g_bkt2[(size_t)row * CAP2];
    const float4* hb = reinterpret_cast<const float4*>(g_h);
    float4 acc = {0.f, 0.f, 0.f, 0.f};
    for (int i = 0; i < n; i++) {
        float4 v = __ldg(&hb[(long long)bkt[i] * 64 + t]);
        acc.x += v.x; acc.y += v.y; acc.z += v.z; acc.w += v.w;
    }
    float inv = (deg > 0) ? 1.0f / (float)deg : 0.0f;
    acc.x *= inv; acc.y *= inv; acc.z *= inv; acc.w *= inv;
    reinterpret_cast<float4*>(sA)[t] = acc;
    reinterpret_cast<float4*>(sH)[t] = hb[(long long)row * 64 + t];
    __syncthreads();                          // all threads are past their deg read
    if (t == 0) g_cnt2[row] = 0;              // self-clean for next call

    if (t < OUT_C) {
        float a = bl2[t];
#pragma unroll 8
        for (int k = 0; k < HID; k++)
            a += sA[k] * __ldg(&Wl2[k * OUT_C + t]) + sH[k] * __ldg(&Wr2[k * OUT_C + t]);
        sO[t] = a;
    }
    __syncthreads();
    if (t == 0) {
        float mx = -1e30f;
        for (int j = 0; j < OUT_C; j++) mx = fmaxf(mx, sO[j]);
        float se = 0.f;
        for (int j = 0; j < OUT_C; j++) se += expf(sO[j] - mx);
        s_mx = mx; s_ls = logf(se);
    }
    __syncthreads();
    if (t < OUT_C) out[(long long)row * OUT_C + t] = sO[t] - s_mx - s_ls;
}

// ---------------- launch ----------------
extern "C" void kernel_launch(void* const* d_in, const int* in_sizes, int n_in,
                              void* d_out, int out_size) {
    const float* x   = (const float*)d_in[0];
    const int*   ei1 = (const int*)d_in[1];     // int32 [2, E1]
    const int*   ei2 = (const int*)d_in[2];     // int32 [2, E2]
    const float* Wl1 = (const float*)d_in[3];
    const float* bl1 = (const float*)d_in[4];
    const float* Wr1 = (const float*)d_in[5];
    const float* Wl2 = (const float*)d_in[6];
    const float* bl2 = (const float*)d_in[7];
    const float* Wr2 = (const float*)d_in[8];
    float* out = (float*)d_out;

    static cudaStream_t s1 = nullptr;
    static cudaEvent_t evF = nullptr, evJ = nullptr;
    if (s1 == nullptr) {
        cudaStreamCreateWithFlags(&s1, cudaStreamNonBlocking);
        cudaEventCreateWithFlags(&evF, cudaEventDisableTiming);
        cudaEventCreateWithFlags(&evJ, cudaEventDisableTiming);
    }

    // fork side stream (submission order tuned so ncu's fixed capture slot
    // lands on k_agg1 / k_gemm1 instead of k_fill_all)
    cudaEventRecord(evF, 0);
    cudaStreamWaitEvent(s1, evF, 0);
    k_prep<<<(KTOT * HID + 255) / 256, 256, 0, s1>>>(Wl1, Wr1);           // #1
    k_fill_all<<<(E1 + E2 + 255) / 256, 256>>>(ei1, ei2);                 // #2 (main)
    k_xcast<<<(N1 * (KP / 2) + 255) / 256, 256, 0, s1>>>(x);              // #3
    cudaEventRecord(evJ, s1);
    k_agg1<<<N1, 128>>>(x);                                               // #4 (main)

    // join, then 128x128 GEMM + fused layer 2
    cudaStreamWaitEvent(0, evJ, 0);
    k_gemm1<<<dim3(176, 2), 256>>>(bl1);                                  // #5
    k_l2<<<N2, 64>>>(Wl2, bl2, Wr2, out);                                 // #6
}

// round 17
// speedup vs baseline: 1.2614x; 1.2614x over previous
#include <cuda_runtime.h>
#include <cuda_bf16.h>
#include <cstdint>

#define N0 585728
#define N1 22528
#define N2 2048
#define E1 563200
#define E2 20480
#define IN_C 602
#define HID 256
#define OUT_C 41
#define KP 608           // padded half-K (602 -> 608)
#define KTOT 1216        // 2*KP
#define NKT 38           // KTOT/32 k-tiles
#define CAP1 96          // bucket capacity layer1 (Poisson λ=25, >8σ)
#define CAP2 64          // layer2 (λ=10)

// -------- scratch (static device globals; no allocation) --------
__device__ __align__(16) __nv_bfloat162 g_a1b[(size_t)N1 * (KP / 2)];  // agg1 bf16 [N1][608]
__device__ __align__(16) __nv_bfloat162 g_xb[(size_t)N1 * (KP / 2)];   // x_dst bf16 [N1][608]
__device__ __align__(16) __nv_bfloat16 g_wbT[(size_t)HID * KTOT];      // W^T bf16 [256][1216]
__device__ __align__(16) float g_h[(size_t)N1 * HID];
__device__ int g_cnt1[N1];
__device__ int g_bkt1[(size_t)N1 * CAP1];
__device__ int g_cnt2[N2];
__device__ int g_bkt2[(size_t)N2 * CAP2];

// ---------------- zero counters ----------------
__global__ void k_zero_cnt() {
    int i = blockIdx.x * blockDim.x + threadIdx.x;
    if (i < N1) g_cnt1[i] = 0;
    if (i < N2) g_cnt2[i] = 0;
}

// ---------------- bucket fill (both layers, one launch) ---------------------
__global__ void k_fill_all(const int* __restrict__ ei1, const int* __restrict__ ei2) {
    int e = blockIdx.x * blockDim.x + threadIdx.x;
    if (e < E1) {
        int dst = ei1[E1 + e];
        int p = atomicAdd(&g_cnt1[dst], 1);
        if (p < CAP1) g_bkt1[(size_t)dst * CAP1 + p] = ei1[e];
    } else if (e < E1 + E2) {
        int f = e - E1;
        int dst = ei2[E2 + f];
        int p = atomicAdd(&g_cnt2[dst], 1);
        if (p < CAP2) g_bkt2[(size_t)dst * CAP2 + p] = ei2[f];
    }
}

// ---------------- weight prep: g_wbT[n][k] bf16, concat+pad -----------------
__global__ void k_prep(const float* __restrict__ Wl1, const float* __restrict__ Wr1) {
    int idx = blockIdx.x * blockDim.x + threadIdx.x;   // k*256+n
    if (idx >= KTOT * HID) return;
    int k = idx >> 8, n = idx & 255;
    float v = 0.f;
    if (k < IN_C)                      v = Wl1[(size_t)k * HID + n];
    else if (k >= KP && k < KP + IN_C) v = Wr1[(size_t)(k - KP) * HID + n];
    g_wbT[(size_t)n * KTOT + k] = __float2bfloat16(v);
}

// ---------------- x_dst -> bf16 padded ----------------
__global__ void k_xcast(const float* __restrict__ x) {
    int idx = blockIdx.x * blockDim.x + threadIdx.x;   // word index, [N1*304]
    if (idx >= N1 * (KP / 2)) return;
    int row = idx / (KP / 2), w = idx % (KP / 2);
    int c = w * 2;
    float a = (c < IN_C)     ? x[(size_t)row * IN_C + c] : 0.f;
    float b = (c + 1 < IN_C) ? x[(size_t)row * IN_C + c + 1] : 0.f;
    g_xb[idx] = __floats2bfloat162_rn(a, b);
}

// ---------------- layer-1 mean aggregation -> bf16 padded -------------------
// Bucket indices staged in SMEM so gather addresses never depend on an
// in-flight global load; 4-edge unroll -> 12 independent gathers in flight.
__global__ void __launch_bounds__(128) k_agg1(const float* __restrict__ x) {
    __shared__ int sb[CAP1];
    int dst = blockIdx.x;
    int t = threadIdx.x;                       // 128 threads
    int deg = g_cnt1[dst];
    int n = min(deg, CAP1);
    if (t < CAP1) sb[t] = g_bkt1[(size_t)dst * CAP1 + t];
    __syncthreads();

    float2 acc0 = {0.f, 0.f}, acc1 = {0.f, 0.f}, acc2 = {0.f, 0.f};
    const float2* xb = reinterpret_cast<const float2*>(x);   // 301 float2/row
    int f2 = t + 256;
    bool g2 = (f2 < 301);
    int i = 0;
    for (; i + 3 < n; i += 4) {
        long long r0 = (long long)sb[i] * 301;
        long long r1 = (long long)sb[i + 1] * 301;
        long long r2 = (long long)sb[i + 2] * 301;
        long long r3 = (long long)sb[i + 3] * 301;
        float2 a0 = __ldg(&xb[r0 + t]),       a1 = __ldg(&xb[r1 + t]);
        float2 a2 = __ldg(&xb[r2 + t]),       a3 = __ldg(&xb[r3 + t]);
        float2 b0 = __ldg(&xb[r0 + t + 128]), b1 = __ldg(&xb[r1 + t + 128]);
        float2 b2 = __ldg(&xb[r2 + t + 128]), b3 = __ldg(&xb[r3 + t + 128]);
        float2 c0 = g2 ? __ldg(&xb[r0 + f2]) : make_float2(0.f, 0.f);
        float2 c1 = g2 ? __ldg(&xb[r1 + f2]) : make_float2(0.f, 0.f);
        float2 c2 = g2 ? __ldg(&xb[r2 + f2]) : make_float2(0.f, 0.f);
        float2 c3 = g2 ? __ldg(&xb[r3 + f2]) : make_float2(0.f, 0.f);
        acc0.x += (a0.x + a1.x) + (a2.x + a3.x);
        acc0.y += (a0.y + a1.y) + (a2.y + a3.y);
        acc1.x += (b0.x + b1.x) + (b2.x + b3.x);
        acc1.y += (b0.y + b1.y) + (b2.y + b3.y);
        acc2.x += (c0.x + c1.x) + (c2.x + c3.x);
        acc2.y += (c0.y + c1.y) + (c2.y + c3.y);
    }
    for (; i < n; i++) {
        long long r0 = (long long)sb[i] * 301;
        float2 a = __ldg(&xb[r0 + t]);
        float2 b = __ldg(&xb[r0 + t + 128]);
        acc0.x += a.x; acc0.y += a.y;
        acc1.x += b.x; acc1.y += b.y;
        if (g2) { float2 c = __ldg(&xb[r0 + f2]); acc2.x += c.x; acc2.y += c.y; }
    }
    float inv = (deg > 0) ? 1.0f / (float)deg : 0.0f;
    __nv_bfloat162* ob = g_a1b + (long long)dst * (KP / 2);    // 304 words/row
    ob[t]       = __floats2bfloat162_rn(acc0.x * inv, acc0.y * inv);
    ob[t + 128] = __floats2bfloat162_rn(acc1.x * inv, acc1.y * inv);
    if (t < 48) {
        int w2 = t + 256;
        ob[w2] = __floats2bfloat162_rn((w2 < 301) ? acc2.x * inv : 0.f,
                                       (w2 < 301) ? acc2.y * inv : 0.f);
    }
}

// ---------------- MMA / ldmatrix / cp.async helpers ----------------
__device__ __forceinline__ void mma_bf16(float& c0, float& c1, float& c2, float& c3,
                                         unsigned a0, unsigned a1, unsigned a2, unsigned a3,
                                         unsigned b0, unsigned b1) {
    asm volatile("mma.sync.aligned.m16n8k16.row.col.f32.bf16.bf16.f32 "
                 "{%0,%1,%2,%3}, {%4,%5,%6,%7}, {%8,%9}, {%0,%1,%2,%3};"
                 : "+f"(c0), "+f"(c1), "+f"(c2), "+f"(c3)
                 : "r"(a0), "r"(a1), "r"(a2), "r"(a3), "r"(b0), "r"(b1));
}
__device__ __forceinline__ void ldsm4(unsigned* r, unsigned addr) {
    asm volatile("ldmatrix.sync.aligned.m8n8.x4.shared.b16 {%0,%1,%2,%3}, [%4];"
                 : "=r"(r[0]), "=r"(r[1]), "=r"(r[2]), "=r"(r[3]) : "r"(addr));
}
__device__ __forceinline__ void cpa16(unsigned saddr, const void* g) {
    asm volatile("cp.async.cg.shared.global [%0], [%1], 16;" :: "r"(saddr), "l"(g));
}
__device__ __forceinline__ void cpa_commit() { asm volatile("cp.async.commit_group;"); }

// ---------------- fused GEMM1 (bf16 MMA, 128x128 tile, 3-stage cp.async) ----
// h = relu([agg1 | x_dst] @ [Wl1;Wr1] + bl1)
// M=22528, K=1216 (padded), N=256. Block 128x128, 8 warps (4m x 2n), warp 32x64.
#define KSW 20
#define NSTG 3
__global__ void __launch_bounds__(256) k_gemm1(const float* __restrict__ bl1) {
    __shared__ __align__(16) unsigned As[NSTG][128 * KSW];   // 30720 B
    __shared__ __align__(16) unsigned Bs[NSTG][128 * KSW];   // 30720 B
    int tid = threadIdx.x;
    int bm = blockIdx.x * 128;
    int bn = blockIdx.y * 128;
    int warp = tid >> 5, lane = tid & 31;
    int wm = (warp & 3) * 32;
    int wn = (warp >> 2) * 64;
    int gid = lane >> 2, tig = lane & 3;

    // cp.async per-thread coords (2 chunks/thread for each of A and B)
    int ar = tid >> 1;                 // row
    int ac = (tid & 1) * 2;            // first 16B chunk (of 4/row)

    const __nv_bfloat16* a1p = reinterpret_cast<const __nv_bfloat16*>(g_a1b);
    const __nv_bfloat16* xbp = reinterpret_cast<const __nv_bfloat16*>(g_xb);

    float acc[2][8][4];
#pragma unroll
    for (int mt = 0; mt < 2; mt++)
#pragma unroll
        for (int nt = 0; nt < 8; nt++)
#pragma unroll
            for (int r = 0; r < 4; r++) acc[mt][nt][r] = 0.f;

    unsigned sA[NSTG], sB[NSTG];
#pragma unroll
    for (int s = 0; s < NSTG; s++) {
        sA[s] = (unsigned)__cvta_generic_to_shared(&As[s][0]);
        sB[s] = (unsigned)__cvta_generic_to_shared(&Bs[s][0]);
    }

    // ldmatrix lane address components
    int a_ro = (lane & 7) + ((lane >> 3) & 1) * 8;
    int a_kw = (lane >> 4) * 4;
    int aoffw[2];
#pragma unroll
    for (int mt = 0; mt < 2; mt++) aoffw[mt] = (wm + mt * 16 + a_ro) * KSW + a_kw;
    int b_ro = (lane & 7) + ((lane >> 4) << 3);
    int b_kw = ((lane >> 3) & 1) * 4;
    int boffw[4];
#pragma unroll
    for (int p = 0; p < 4; p++) boffw[p] = (wn + p * 16 + b_ro) * KSW + b_kw;

    auto load_tile = [&](int buf, int kt) {
        const __nv_bfloat16* src = (kt < 19) ? a1p : xbp;
        int k0 = ((kt < 19) ? kt : kt - 19) * 32;
#pragma unroll
        for (int i = 0; i < 2; i++) {
            int c = ac + i;
            const void* g = src + ((size_t)(bm + ar)) * KP + k0 + c * 8;
            cpa16(sA[buf] + (ar * KSW + c * 4) * 4, g);
        }
#pragma unroll
        for (int i = 0; i < 2; i++) {
            int c = ac + i;
            const void* g = g_wbT + ((size_t)(bn + ar)) * KTOT + kt * 32 + c * 8;
            cpa16(sB[buf] + (ar * KSW + c * 4) * 4, g);
        }
    };

    load_tile(0, 0); cpa_commit();
    load_tile(1, 1); cpa_commit();

    for (int kt = 0; kt < NKT; kt++) {
        int st = kt % NSTG;
        asm volatile("cp.async.wait_group 1;");
        __syncthreads();
        if (kt + 2 < NKT) { load_tile((kt + 2) % NSTG, kt + 2); cpa_commit(); }

#pragma unroll
        for (int half = 0; half < 2; half++) {
            unsigned af[2][4], bf[4][4];
#pragma unroll
            for (int mt = 0; mt < 2; mt++)
                ldsm4(af[mt], sA[st] + (aoffw[mt] + half * 8) * 4);
#pragma unroll
            for (int p = 0; p < 4; p++)
                ldsm4(bf[p], sB[st] + (boffw[p] + half * 8) * 4);
#pragma unroll
            for (int mt = 0; mt < 2; mt++)
#pragma unroll
                for (int nt = 0; nt < 8; nt++) {
                    int p = nt >> 1, q = (nt & 1) * 2;
                    mma_bf16(acc[mt][nt][0], acc[mt][nt][1], acc[mt][nt][2], acc[mt][nt][3],
                             af[mt][0], af[mt][1], af[mt][2], af[mt][3],
                             bf[p][q], bf[p][q + 1]);
                }
        }
    }

    // epilogue: bias + relu
#pragma unroll
    for (int nt = 0; nt < 8; nt++) {
        int c = bn + wn + nt * 8 + tig * 2;
        float b0 = bl1[c], b1 = bl1[c + 1];
#pragma unroll
        for (int mt = 0; mt < 2; mt++) {
            int r0 = bm + wm + mt * 16 + gid;
            float2 o0, o1;
            o0.x = fmaxf(acc[mt][nt][0] + b0, 0.f);
            o0.y = fmaxf(acc[mt][nt][1] + b1, 0.f);
            o1.x = fmaxf(acc[mt][nt][2] + b0, 0.f);
            o1.y = fmaxf(acc[mt][nt][3] + b1, 0.f);
            *reinterpret_cast<float2*>(&g_h[(long long)r0 * 256 + c]) = o0;
            *reinterpret_cast<float2*>(&g_h[(long long)(r0 + 8) * 256 + c]) = o1;
        }
    }
}

// ---------------- fused layer 2: agg2 + GEMM2 + bias + log_softmax ----------
__global__ void __launch_bounds__(64) k_l2(const float* __restrict__ Wl2,
                                           const float* __restrict__ bl2,
                                           const float* __restrict__ Wr2,
                                           float* __restrict__ out) {
    __shared__ __align__(16) float sA[HID];
    __shared__ __align__(16) float sH[HID];
    __shared__ float sO[OUT_C];
    __shared__ float s_mx, s_ls;
    int row = blockIdx.x, t = threadIdx.x;    // 64 threads, one float4 lane each

    int deg = g_cnt2[row];
    int n = min(deg, CAP2);
    const int* bkt = &g_bkt2[(size_t)row * CAP2];
    const float4* hb = reinterpret_cast<const float4*>(g_h);
    float4 acc = {0.f, 0.f, 0.f, 0.f};
    for (int i = 0; i < n; i++) {
        float4 v = __ldg(&hb[(long long)bkt[i] * 64 + t]);
        acc.x += v.x; acc.y += v.y; acc.z += v.z; acc.w += v.w;
    }
    float inv = (deg > 0) ? 1.0f / (float)deg : 0.0f;
    acc.x *= inv; acc.y *= inv; acc.z *= inv; acc.w *= inv;
    reinterpret_cast<float4*>(sA)[t] = acc;
    reinterpret_cast<float4*>(sH)[t] = hb[(long long)row * 64 + t];
    __syncthreads();

    if (t < OUT_C) {
        float a = bl2[t];
#pragma unroll 8
        for (int k = 0; k < HID; k++)
            a += sA[k] * __ldg(&Wl2[k * OUT_C + t]) + sH[k] * __ldg(&Wr2[k * OUT_C + t]);
        sO[t] = a;
    }
    __syncthreads();
    if (t == 0) {
        float mx = -1e30f;
        for (int j = 0; j < OUT_C; j++) mx = fmaxf(mx, sO[j]);
        float se = 0.f;
        for (int j = 0; j < OUT_C; j++) se += expf(sO[j] - mx);
        s_mx = mx; s_ls = logf(se);
    }
    __syncthreads();
    if (t < OUT_C) out[(long long)row * OUT_C + t] = sO[t] - s_mx - s_ls;
}

// ---------------- launch ----------------
extern "C" void kernel_launch(void* const* d_in, const int* in_sizes, int n_in,
                              void* d_out, int out_size) {
    const float* x   = (const float*)d_in[0];
    const int*   ei1 = (const int*)d_in[1];     // int32 [2, E1]
    const int*   ei2 = (const int*)d_in[2];     // int32 [2, E2]
    const float* Wl1 = (const float*)d_in[3];
    const float* bl1 = (const float*)d_in[4];
    const float* Wr1 = (const float*)d_in[5];
    const float* Wl2 = (const float*)d_in[6];
    const float* bl2 = (const float*)d_in[7];
    const float* Wr2 = (const float*)d_in[8];
    float* out = (float*)d_out;

    static cudaStream_t s1 = nullptr;
    static cudaEvent_t evF = nullptr, evJ = nullptr;
    if (s1 == nullptr) {
        cudaStreamCreateWithFlags(&s1, cudaStreamNonBlocking);
        cudaEventCreateWithFlags(&evF, cudaEventDisableTiming);
        cudaEventCreateWithFlags(&evJ, cudaEventDisableTiming);
    }

    // fork: weight/x conversion on side stream
    cudaEventRecord(evF, 0);
    cudaStreamWaitEvent(s1, evF, 0);
    k_prep<<<(KTOT * HID + 255) / 256, 256, 0, s1>>>(Wl1, Wr1);
    k_xcast<<<(N1 * (KP / 2) + 255) / 256, 256, 0, s1>>>(x);
    cudaEventRecord(evJ, s1);

    // main chain: bucket build -> aggregation
    k_zero_cnt<<<(N1 + 255) / 256, 256>>>();
    k_fill_all<<<(E1 + E2 + 255) / 256, 256>>>(ei1, ei2);
    k_agg1<<<N1, 128>>>(x);

    // join, then 128x128 GEMM + fused layer 2
    cudaStreamWaitEvent(0, evJ, 0);
    k_gemm1<<<dim3(176, 2), 256>>>(bl1);
    k_l2<<<N2, 64>>>(Wl2, bl2, Wr2, out);
}